// round 16
// baseline (speedup 1.0000x reference)
#include <cuda_runtime.h>
#include <cuda_fp16.h>
#include <cstdint>

// ---------------------------------------------------------------------------
// Problem constants
// ---------------------------------------------------------------------------
#define NUM_MODALS 4
#define SHARED_IDX 3
#define CDIM       768
#define RANK       16
#define ROWS_PER_M 8192
#define TOTAL_ROWS 32768

// fp16 operand storage (device globals = allowed scratch)
__device__ __half g_Xq[TOTAL_ROWS * CDIM];
__device__ __half g_Wq[NUM_MODALS * CDIM * CDIM];

// ---------------------------------------------------------------------------
// Helpers
// ---------------------------------------------------------------------------
__device__ __forceinline__ uint32_t smem_u32(const void* p) {
    uint32_t a;
    asm("{ .reg .u64 t; cvta.to.shared.u64 t, %1; cvt.u32.u64 %0, t; }"
        : "=r"(a) : "l"(p));
    return a;
}
__device__ __forceinline__ void cp_async16(uint32_t dst, const void* src) {
    asm volatile("cp.async.cg.shared.global [%0], [%1], 16;"
                 :: "r"(dst), "l"(src) : "memory");
}
__device__ __forceinline__ void cp_commit() {
    asm volatile("cp.async.commit_group;" ::: "memory");
}
template <int N>
__device__ __forceinline__ void cp_wait() {
    asm volatile("cp.async.wait_group %0;" :: "n"(N) : "memory");
}
__device__ __forceinline__ void ldm_x4(uint32_t& r0, uint32_t& r1,
                                       uint32_t& r2, uint32_t& r3,
                                       uint32_t addr) {
    asm volatile("ldmatrix.sync.aligned.m8n8.x4.shared.b16 {%0,%1,%2,%3}, [%4];"
                 : "=r"(r0), "=r"(r1), "=r"(r2), "=r"(r3) : "r"(addr));
}
__device__ __forceinline__ void mma_f16(float& d0, float& d1, float& d2, float& d3,
                                        uint32_t a0, uint32_t a1, uint32_t a2, uint32_t a3,
                                        uint32_t b0, uint32_t b1) {
    asm volatile("mma.sync.aligned.m16n8k16.row.col.f32.f16.f16.f32 "
                 "{%0,%1,%2,%3}, {%4,%5,%6,%7}, {%8,%9}, {%0,%1,%2,%3};"
                 : "+f"(d0), "+f"(d1), "+f"(d2), "+f"(d3)
                 : "r"(a0), "r"(a1), "r"(a2), "r"(a3), "r"(b0), "r"(b1));
}

// ---------------------------------------------------------------------------
// Kernel 1: fused prep, vectorized (round 15 proven).
//   blocks [0, XBLK)      : convert x -> fp16 (2 float4 quads / thread)
//   blocks [XBLK, TOTALB) : W_eff = Wp + Bw3*A3 + Bwm*Am -> fp16 (4 c / thread)
// ---------------------------------------------------------------------------
#define XQUADS  (TOTAL_ROWS * CDIM / 4)           // 6291456 float4 quads
#define XBLK    (XQUADS / 512)                    // 12288
#define WQUADS  (NUM_MODALS * CDIM * CDIM / 4)    // 589824
#define WBLK    (WQUADS / 256)                    // 2304
#define TOTALB  (XBLK + WBLK)                     // 14592

__global__ __launch_bounds__(256)
void prep_kernel(const float* __restrict__ x,
                 const float* __restrict__ Wp,
                 const float* __restrict__ A,
                 const float* __restrict__ Bw) {
    const int b = blockIdx.x;
    if (b < XBLK) {
        const int i0 = b * 512 + threadIdx.x;
        const int i1 = i0 + 256;
        float4 v0 = reinterpret_cast<const float4*>(x)[i0];
        float4 v1 = reinterpret_cast<const float4*>(x)[i1];
        __half2* H = reinterpret_cast<__half2*>(g_Xq);
        H[i0 * 2 + 0] = __floats2half2_rn(v0.x, v0.y);
        H[i0 * 2 + 1] = __floats2half2_rn(v0.z, v0.w);
        H[i1 * 2 + 0] = __floats2half2_rn(v1.x, v1.y);
        H[i1 * 2 + 1] = __floats2half2_rn(v1.z, v1.w);
    } else {
        const int q = (b - XBLK) * 256 + threadIdx.x;
        const int c4 = (q * 4) % CDIM;
        const int o  = (q * 4 / CDIM) % CDIM;
        const int m  = q * 4 / (CDIM * CDIM);

        const float* A3 = A + SHARED_IDX * RANK * CDIM;
        const float* B3 = Bw + SHARED_IDX * CDIM * RANK + o * RANK;
        const float* Am = A + m * RANK * CDIM;
        const float* Bm = Bw + m * CDIM * RANK + o * RANK;

        float4 s = *reinterpret_cast<const float4*>(Wp + o * CDIM + c4);
#pragma unroll
        for (int r = 0; r < RANK; r++) {
            const float b3 = B3[r];
            const float bm = Bm[r];
            const float4 a3 = *reinterpret_cast<const float4*>(A3 + r * CDIM + c4);
            const float4 am = *reinterpret_cast<const float4*>(Am + r * CDIM + c4);
            s.x += b3 * a3.x + bm * am.x;
            s.y += b3 * a3.y + bm * am.y;
            s.z += b3 * a3.z + bm * am.z;
            s.w += b3 * a3.w + bm * am.w;
        }
        __half2 h0 = __floats2half2_rn(s.x, s.y);
        __half2 h1 = __floats2half2_rn(s.z, s.w);
        uint2 pk;
        pk.x = *reinterpret_cast<uint32_t*>(&h0);
        pk.y = *reinterpret_cast<uint32_t*>(&h1);
        *reinterpret_cast<uint2*>(g_Wq + (size_t)q * 4) = pk;
    }
}

// ---------------------------------------------------------------------------
// Kernel 2: fp16 GEMM via mma.sync (fp32 accumulate).
//   out[row][o] = sum_c x[row][c]*Weff[m][o][c] + bp[o]
// CTA tile 128x128, 128 threads (4 warps, 2x2), warp tile 64x64.
// K-chunk 32, FIVE-stage cp.async pipeline (4 chunks in flight), 2 CTAs/SM.
// ---------------------------------------------------------------------------
#define BM     128
#define KC2    32                 // fp16 K elems per chunk
#define NCHK   (CDIM / KC2)       // 24
#define LDT    80                 // smem bytes per tile row (64 data + 16 pad)
#define ATB    (BM * LDT)         // 10240 bytes (A tile)
#define BTB    (128 * LDT)        // 10240 bytes (B tile)
#define STB    (ATB + BTB)        // 20480 bytes per stage
#define OFF_A  0
#define OFF_B  ATB
#define STAGES 5
#define SMEM_TOTAL (STAGES * STB) // 102400 -> 2 CTAs/SM (204800 <= 228KB)

__device__ __forceinline__ void issue_chunk(const __half* __restrict__ xq,
                                            const __half* __restrict__ wq,
                                            int row0, int col0, int kbase,
                                            uint32_t sstage, int tid) {
    // A tile: 128 rows x 64B = 512 x 16B transfers
#pragma unroll
    for (int i = 0; i < 4; i++) {
        int idx = i * 128 + tid;       // 0..511
        int row = idx >> 2;            // 0..127
        int ch  = idx & 3;
        uint32_t soff = row * LDT + ch * 16;
        size_t goff = (size_t)(row0 + row) * CDIM + kbase + ch * 8;
        cp_async16(sstage + OFF_A + soff, xq + goff);
    }
    // B tile: 128 rows x 64B = 512 x 16B transfers
#pragma unroll
    for (int i = 0; i < 4; i++) {
        int idx = i * 128 + tid;
        int row = idx >> 2;
        int ch  = idx & 3;
        uint32_t soff = row * LDT + ch * 16;
        size_t goff = (size_t)(col0 + row) * CDIM + kbase + ch * 8;
        cp_async16(sstage + OFF_B + soff, wq + goff);
    }
    cp_commit();
}

__global__ __launch_bounds__(128, 2)
void lora_mma_gemm(const float* __restrict__ bp, float* __restrict__ out) {
    extern __shared__ char smem[];
    const uint32_t sbase = smem_u32(smem);
    const int tid  = threadIdx.x;
    const int wid  = tid >> 5;
    const int lane = tid & 31;
    const int warp_m = wid >> 1;       // 0..1  (64 rows each)
    const int warp_n = wid & 1;        // 0..1  (64 cols each)

    const int row0 = blockIdx.y * BM;
    const int col0 = blockIdx.x * 128;
    const int modality = row0 / ROWS_PER_M;
    const __half* Wq = g_Wq + (size_t)modality * CDIM * CDIM;

    float acc[4][8][4];
#pragma unroll
    for (int i = 0; i < 4; i++)
#pragma unroll
        for (int j = 0; j < 8; j++)
#pragma unroll
            for (int r = 0; r < 4; r++) acc[i][j][r] = 0.f;

    // ldmatrix lane addressing
    const int mat = lane >> 3;         // which 8x8 tile (0..3)
    const int mr  = lane & 7;          // row within tile
    const int a_row  = warp_m * 64 + (mat & 1) * 8 + mr;     // + i*16
    const int a_colb = (mat >> 1) * 16;                      // bytes, + kk*32
    const int b_row  = warp_n * 64 + (mat >> 1) * 8 + mr;    // + jh*16
    const int b_colb = (mat & 1) * 16;                       // bytes, + kk*32

    // Prologue: 4 chunks in flight
    issue_chunk(g_Xq, Wq, row0, col0, 0,       sbase + 0 * STB, tid);
    issue_chunk(g_Xq, Wq, row0, col0, KC2,     sbase + 1 * STB, tid);
    issue_chunk(g_Xq, Wq, row0, col0, 2 * KC2, sbase + 2 * STB, tid);
    issue_chunk(g_Xq, Wq, row0, col0, 3 * KC2, sbase + 3 * STB, tid);

    for (int c = 0; c < NCHK; c++) {
        // wait until chunk c landed: pending = #chunks issued beyond c
        if (c + 1 >= NCHK)      cp_wait<0>();
        else if (c + 2 >= NCHK) cp_wait<1>();
        else if (c + 3 >= NCHK) cp_wait<2>();
        else                    cp_wait<3>();
        __syncthreads();   // also protects slot (c-1)%5 from the issue below

        if (c + 4 < NCHK)
            issue_chunk(g_Xq, Wq, row0, col0, (c + 4) * KC2,
                        sbase + ((c + 4) % STAGES) * STB, tid);

        const uint32_t st = sbase + (c % STAGES) * STB;
        const uint32_t sA = st + OFF_A, sB = st + OFF_B;

#pragma unroll
        for (int kk = 0; kk < 2; kk++) {
            uint32_t bq[8][2];
#pragma unroll
            for (int jh = 0; jh < 4; jh++) {      // 4 x 16-col fragments
                uint32_t boff = (uint32_t)(b_row + jh * 16) * LDT + kk * 32 + b_colb;
                uint32_t r0, r1, r2, r3;
                ldm_x4(r0, r1, r2, r3, sB + boff);
                bq[2 * jh][0] = r0; bq[2 * jh][1] = r1;
                bq[2 * jh + 1][0] = r2; bq[2 * jh + 1][1] = r3;
            }
#pragma unroll
            for (int i = 0; i < 4; i++) {
                uint32_t aoff = (uint32_t)(a_row + i * 16) * LDT + kk * 32 + a_colb;
                uint32_t a0, a1, a2, a3;
                ldm_x4(a0, a1, a2, a3, sA + aoff);
#pragma unroll
                for (int j = 0; j < 8; j++)
                    mma_f16(acc[i][j][0], acc[i][j][1], acc[i][j][2], acc[i][j][3],
                            a0, a1, a2, a3, bq[j][0], bq[j][1]);
            }
        }
    }
    __syncthreads();

    // Epilogue: bias + store. mma C frag: lane t -> rows (t/4, t/4+8), cols (t%4)*2..+1
    const int gID = lane >> 2;
    const int tg  = lane & 3;
#pragma unroll
    for (int j = 0; j < 8; j++) {
        const int col = col0 + warp_n * 64 + j * 8 + tg * 2;
        const float2 bb = *reinterpret_cast<const float2*>(bp + col);
#pragma unroll
        for (int i = 0; i < 4; i++) {
            const int row = row0 + warp_m * 64 + i * 16 + gID;
            float2 v0 = make_float2(acc[i][j][0] + bb.x, acc[i][j][1] + bb.y);
            float2 v1 = make_float2(acc[i][j][2] + bb.x, acc[i][j][3] + bb.y);
            *reinterpret_cast<float2*>(out + (size_t)row * CDIM + col) = v0;
            *reinterpret_cast<float2*>(out + (size_t)(row + 8) * CDIM + col) = v1;
        }
    }
}

// ---------------------------------------------------------------------------
// Launch
// ---------------------------------------------------------------------------
extern "C" void kernel_launch(void* const* d_in, const int* in_sizes, int n_in,
                              void* d_out, int out_size) {
    const float* x  = (const float*)d_in[0];  // [32, 1024, 768]
    const float* Wp = (const float*)d_in[1];  // [768, 768]
    const float* bp = (const float*)d_in[2];  // [768]
    const float* A  = (const float*)d_in[3];  // [4, 16, 768]
    const float* Bw = (const float*)d_in[4];  // [4, 768, 16]
    float* out = (float*)d_out;

    prep_kernel<<<TOTALB, 256>>>(x, Wp, A, Bw);
    {
        cudaFuncSetAttribute(lora_mma_gemm,
                             cudaFuncAttributeMaxDynamicSharedMemorySize, SMEM_TOTAL);
        dim3 grid(CDIM / 128, TOTAL_ROWS / BM);  // (6, 256)
        lora_mma_gemm<<<grid, 128, SMEM_TOTAL>>>(bp, out);
    }
}

// round 17
// speedup vs baseline: 1.0306x; 1.0306x over previous
#include <cuda_runtime.h>
#include <cuda_fp16.h>
#include <cstdint>

// ---------------------------------------------------------------------------
// Problem constants
// ---------------------------------------------------------------------------
#define NUM_MODALS 4
#define SHARED_IDX 3
#define CDIM       768
#define RANK       16
#define ROWS_PER_M 8192
#define TOTAL_ROWS 32768

// fp16 operand storage (device globals = allowed scratch)
__device__ __half g_Xq[TOTAL_ROWS * CDIM];
__device__ __half g_Wq[NUM_MODALS * CDIM * CDIM];

// ---------------------------------------------------------------------------
// Helpers
// ---------------------------------------------------------------------------
__device__ __forceinline__ uint32_t smem_u32(const void* p) {
    uint32_t a;
    asm("{ .reg .u64 t; cvta.to.shared.u64 t, %1; cvt.u32.u64 %0, t; }"
        : "=r"(a) : "l"(p));
    return a;
}
__device__ __forceinline__ void cp_async16(uint32_t dst, const void* src) {
    asm volatile("cp.async.cg.shared.global [%0], [%1], 16;"
                 :: "r"(dst), "l"(src) : "memory");
}
__device__ __forceinline__ void cp_commit() {
    asm volatile("cp.async.commit_group;" ::: "memory");
}
template <int N>
__device__ __forceinline__ void cp_wait() {
    asm volatile("cp.async.wait_group %0;" :: "n"(N) : "memory");
}
__device__ __forceinline__ void ldm_x4(uint32_t& r0, uint32_t& r1,
                                       uint32_t& r2, uint32_t& r3,
                                       uint32_t addr) {
    asm volatile("ldmatrix.sync.aligned.m8n8.x4.shared.b16 {%0,%1,%2,%3}, [%4];"
                 : "=r"(r0), "=r"(r1), "=r"(r2), "=r"(r3) : "r"(addr));
}
__device__ __forceinline__ void mma_f16(float& d0, float& d1, float& d2, float& d3,
                                        uint32_t a0, uint32_t a1, uint32_t a2, uint32_t a3,
                                        uint32_t b0, uint32_t b1) {
    asm volatile("mma.sync.aligned.m16n8k16.row.col.f32.f16.f16.f32 "
                 "{%0,%1,%2,%3}, {%4,%5,%6,%7}, {%8,%9}, {%0,%1,%2,%3};"
                 : "+f"(d0), "+f"(d1), "+f"(d2), "+f"(d3)
                 : "r"(a0), "r"(a1), "r"(a2), "r"(a3), "r"(b0), "r"(b1));
}

// ---------------------------------------------------------------------------
// Kernel 1: fused prep, vectorized x4 per thread.
//   blocks [0, XBLK)      : convert x -> fp16 (2 float4 quads / thread)
//   blocks [XBLK, TOTALB) : W_eff = Wp + Bw3*A3 + Bwm*Am -> fp16 (4 c / thread)
// ---------------------------------------------------------------------------
#define XQUADS  (TOTAL_ROWS * CDIM / 4)           // 6291456 float4 quads
#define XBLK    (XQUADS / 512)                    // 12288 (2 quads/thread, 256 thr)
#define WQUADS  (NUM_MODALS * CDIM * CDIM / 4)    // 589824 (4 c / thread)
#define WBLK    (WQUADS / 256)                    // 2304
#define TOTALB  (XBLK + WBLK)                     // 14592

__global__ __launch_bounds__(256)
void prep_kernel(const float* __restrict__ x,
                 const float* __restrict__ Wp,
                 const float* __restrict__ A,
                 const float* __restrict__ Bw) {
    const int b = blockIdx.x;
    if (b < XBLK) {
        // two independent quads per thread (MLP=2)
        const int i0 = b * 512 + threadIdx.x;          // quad index 1
        const int i1 = i0 + 256;                       // quad index 2
        float4 v0 = reinterpret_cast<const float4*>(x)[i0];
        float4 v1 = reinterpret_cast<const float4*>(x)[i1];
        __half2* H = reinterpret_cast<__half2*>(g_Xq);
        H[i0 * 2 + 0] = __floats2half2_rn(v0.x, v0.y);
        H[i0 * 2 + 1] = __floats2half2_rn(v0.z, v0.w);
        H[i1 * 2 + 0] = __floats2half2_rn(v1.x, v1.y);
        H[i1 * 2 + 1] = __floats2half2_rn(v1.z, v1.w);
    } else {
        // 4 consecutive c per thread; coefficients hoisted per-o
        const int q = (b - XBLK) * 256 + threadIdx.x;  // quad index into W
        const int c4 = (q * 4) % CDIM;                 // c base (multiple of 4)
        const int o  = (q * 4 / CDIM) % CDIM;
        const int m  = q * 4 / (CDIM * CDIM);

        const float* A3 = A + SHARED_IDX * RANK * CDIM;
        const float* B3 = Bw + SHARED_IDX * CDIM * RANK + o * RANK;
        const float* Am = A + m * RANK * CDIM;
        const float* Bm = Bw + m * CDIM * RANK + o * RANK;

        float4 s = *reinterpret_cast<const float4*>(Wp + o * CDIM + c4);
#pragma unroll
        for (int r = 0; r < RANK; r++) {
            const float b3 = B3[r];                // uniform per o -> broadcast
            const float bm = Bm[r];
            const float4 a3 = *reinterpret_cast<const float4*>(A3 + r * CDIM + c4);
            const float4 am = *reinterpret_cast<const float4*>(Am + r * CDIM + c4);
            s.x += b3 * a3.x + bm * am.x;
            s.y += b3 * a3.y + bm * am.y;
            s.z += b3 * a3.z + bm * am.z;
            s.w += b3 * a3.w + bm * am.w;
        }
        __half2 h0 = __floats2half2_rn(s.x, s.y);
        __half2 h1 = __floats2half2_rn(s.z, s.w);
        uint2 pk;
        pk.x = *reinterpret_cast<uint32_t*>(&h0);
        pk.y = *reinterpret_cast<uint32_t*>(&h1);
        *reinterpret_cast<uint2*>(g_Wq + (size_t)q * 4) = pk;
    }
}

// ---------------------------------------------------------------------------
// Kernel 2: fp16 GEMM via mma.sync (fp32 accumulate) — converged config.
//   out[row][o] = sum_c x[row][c]*Weff[m][o][c] + bp[o]
// CTA tile 128x128, 128 threads (4 warps, 2x2), warp tile 64x64.
// K-chunk 32, 4-stage cp.async pipeline (3 chunks in flight), 2 CTAs/SM.
// ---------------------------------------------------------------------------
#define BM     128
#define KC2    32                 // fp16 K elems per chunk
#define NCHK   (CDIM / KC2)       // 24
#define LDT    80                 // smem bytes per tile row (64 data + 16 pad)
#define ATB    (BM * LDT)         // 10240 bytes (A tile)
#define BTB    (128 * LDT)        // 10240 bytes (B tile)
#define STB    (ATB + BTB)        // 20480 bytes per stage
#define OFF_A  0
#define OFF_B  ATB
#define STAGES 4
#define SMEM_TOTAL (STAGES * STB) // 81920  -> 2 CTAs/SM

__device__ __forceinline__ void issue_chunk(const __half* __restrict__ xq,
                                            const __half* __restrict__ wq,
                                            int row0, int col0, int kbase,
                                            uint32_t sstage, int tid) {
    // A tile: 128 rows x 64B = 512 x 16B transfers
#pragma unroll
    for (int i = 0; i < 4; i++) {
        int idx = i * 128 + tid;       // 0..511
        int row = idx >> 2;            // 0..127
        int ch  = idx & 3;
        uint32_t soff = row * LDT + ch * 16;
        size_t goff = (size_t)(row0 + row) * CDIM + kbase + ch * 8;
        cp_async16(sstage + OFF_A + soff, xq + goff);
    }
    // B tile: 128 rows x 64B = 512 x 16B transfers
#pragma unroll
    for (int i = 0; i < 4; i++) {
        int idx = i * 128 + tid;
        int row = idx >> 2;
        int ch  = idx & 3;
        uint32_t soff = row * LDT + ch * 16;
        size_t goff = (size_t)(col0 + row) * CDIM + kbase + ch * 8;
        cp_async16(sstage + OFF_B + soff, wq + goff);
    }
    cp_commit();
}

__global__ __launch_bounds__(128, 2)
void lora_mma_gemm(const float* __restrict__ bp, float* __restrict__ out) {
    extern __shared__ char smem[];
    const uint32_t sbase = smem_u32(smem);
    const int tid  = threadIdx.x;
    const int wid  = tid >> 5;
    const int lane = tid & 31;
    const int warp_m = wid >> 1;       // 0..1  (64 rows each)
    const int warp_n = wid & 1;        // 0..1  (64 cols each)

    const int row0 = blockIdx.y * BM;
    const int col0 = blockIdx.x * 128;
    const int modality = row0 / ROWS_PER_M;
    const __half* Wq = g_Wq + (size_t)modality * CDIM * CDIM;

    float acc[4][8][4];
#pragma unroll
    for (int i = 0; i < 4; i++)
#pragma unroll
        for (int j = 0; j < 8; j++)
#pragma unroll
            for (int r = 0; r < 4; r++) acc[i][j][r] = 0.f;

    // ldmatrix lane addressing
    const int mat = lane >> 3;         // which 8x8 tile (0..3)
    const int mr  = lane & 7;          // row within tile
    const int a_row  = warp_m * 64 + (mat & 1) * 8 + mr;     // + i*16
    const int a_colb = (mat >> 1) * 16;                      // bytes, + kk*32
    const int b_row  = warp_n * 64 + (mat >> 1) * 8 + mr;    // + jh*16
    const int b_colb = (mat & 1) * 16;                       // bytes, + kk*32

    // Prologue: 3 chunks in flight
    issue_chunk(g_Xq, Wq, row0, col0, 0,       sbase + 0 * STB, tid);
    issue_chunk(g_Xq, Wq, row0, col0, KC2,     sbase + 1 * STB, tid);
    issue_chunk(g_Xq, Wq, row0, col0, 2 * KC2, sbase + 2 * STB, tid);

    for (int c = 0; c < NCHK; c++) {
        if (c + 1 >= NCHK)      cp_wait<0>();
        else if (c + 2 >= NCHK) cp_wait<1>();
        else                    cp_wait<2>();
        __syncthreads();   // also protects slot (c-1)%4 from the issue below

        if (c + 3 < NCHK)
            issue_chunk(g_Xq, Wq, row0, col0, (c + 3) * KC2,
                        sbase + ((c + 3) % STAGES) * STB, tid);

        const uint32_t st = sbase + (c % STAGES) * STB;
        const uint32_t sA = st + OFF_A, sB = st + OFF_B;

#pragma unroll
        for (int kk = 0; kk < 2; kk++) {
            uint32_t bq[8][2];
#pragma unroll
            for (int jh = 0; jh < 4; jh++) {      // 4 x 16-col fragments
                uint32_t boff = (uint32_t)(b_row + jh * 16) * LDT + kk * 32 + b_colb;
                uint32_t r0, r1, r2, r3;
                ldm_x4(r0, r1, r2, r3, sB + boff);
                bq[2 * jh][0] = r0; bq[2 * jh][1] = r1;
                bq[2 * jh + 1][0] = r2; bq[2 * jh + 1][1] = r3;
            }
#pragma unroll
            for (int i = 0; i < 4; i++) {
                uint32_t aoff = (uint32_t)(a_row + i * 16) * LDT + kk * 32 + a_colb;
                uint32_t a0, a1, a2, a3;
                ldm_x4(a0, a1, a2, a3, sA + aoff);
#pragma unroll
                for (int j = 0; j < 8; j++)
                    mma_f16(acc[i][j][0], acc[i][j][1], acc[i][j][2], acc[i][j][3],
                            a0, a1, a2, a3, bq[j][0], bq[j][1]);
            }
        }
    }
    __syncthreads();

    // Epilogue: bias + store. mma C frag: lane t -> rows (t/4, t/4+8), cols (t%4)*2..+1
    const int gID = lane >> 2;
    const int tg  = lane & 3;
#pragma unroll
    for (int j = 0; j < 8; j++) {
        const int col = col0 + warp_n * 64 + j * 8 + tg * 2;
        const float2 bb = *reinterpret_cast<const float2*>(bp + col);
#pragma unroll
        for (int i = 0; i < 4; i++) {
            const int row = row0 + warp_m * 64 + i * 16 + gID;
            float2 v0 = make_float2(acc[i][j][0] + bb.x, acc[i][j][1] + bb.y);
            float2 v1 = make_float2(acc[i][j][2] + bb.x, acc[i][j][3] + bb.y);
            *reinterpret_cast<float2*>(out + (size_t)row * CDIM + col) = v0;
            *reinterpret_cast<float2*>(out + (size_t)(row + 8) * CDIM + col) = v1;
        }
    }
}

// ---------------------------------------------------------------------------
// Launch
// ---------------------------------------------------------------------------
extern "C" void kernel_launch(void* const* d_in, const int* in_sizes, int n_in,
                              void* d_out, int out_size) {
    const float* x  = (const float*)d_in[0];  // [32, 1024, 768]
    const float* Wp = (const float*)d_in[1];  // [768, 768]
    const float* bp = (const float*)d_in[2];  // [768]
    const float* A  = (const float*)d_in[3];  // [4, 16, 768]
    const float* Bw = (const float*)d_in[4];  // [4, 768, 16]
    float* out = (float*)d_out;

    prep_kernel<<<TOTALB, 256>>>(x, Wp, A, Bw);
    {
        cudaFuncSetAttribute(lora_mma_gemm,
                             cudaFuncAttributeMaxDynamicSharedMemorySize, SMEM_TOTAL);
        dim3 grid(CDIM / 128, TOTAL_ROWS / BM);  // (6, 256)
        lora_mma_gemm<<<grid, 128, SMEM_TOTAL>>>(bp, out);
    }
}